// round 1
// baseline (speedup 1.0000x reference)
#include <cuda_runtime.h>

#define Bsz  4
#define Nn   20000
#define Ee   320000
#define CINc 32
#define COUTc 32
#define Kk   16
#define Mm   2

// Scratch: fT (B,N,CIN) and f_out accumulator (B,N,CIN)
__device__ float g_fT[Bsz * Nn * CINc];
__device__ float g_fout[Bsz * Nn * CINc];

// ---------------------------------------------------------------------------
// Kernel 1: transpose f (B,CIN,N) -> fT (B,N,CIN), zero f_out
// grid (N/32=625, B), block (32,8)
// ---------------------------------------------------------------------------
__global__ void prep_kernel(const float* __restrict__ f)
{
    __shared__ float tile[32][33];
    const int b  = blockIdx.y;
    const int n0 = blockIdx.x * 32;
    const int tx = threadIdx.x;   // 0..31
    const int ty = threadIdx.y;   // 0..7

#pragma unroll
    for (int r = 0; r < 4; r++) {
        int ci = ty + 8 * r;
        tile[ci][tx] = f[((long)b * CINc + ci) * Nn + n0 + tx];
    }
    __syncthreads();
#pragma unroll
    for (int r = 0; r < 4; r++) {
        int nl = ty + 8 * r;
        long idx = ((long)b * Nn + n0 + nl) * CINc + tx;
        g_fT[idx]   = tile[tx][nl];
        g_fout[idx] = 0.0f;
    }
}

// ---------------------------------------------------------------------------
// Kernel 2: edge scatter. One warp per edge-measure (grid-stride).
// lane = output channel i. Lanes 0..15 compute P[k],Q[k].
// grid (NB, 2): blockIdx.y = measure m. block 256 (8 warps).
// ---------------------------------------------------------------------------
__global__ void __launch_bounds__(256) edge_kernel(
    const float* __restrict__ bases_c,
    const float* __restrict__ bases_s,
    const float* __restrict__ nodes,
    const float* __restrict__ nvec,
    const int*   __restrict__ de,
    const float* __restrict__ nodew,
    const float* __restrict__ wc,
    const float* __restrict__ ws,
    const float* __restrict__ w0)
{
    const int m     = blockIdx.y;
    const int lane  = threadIdx.x & 31;
    const int warp  = (blockIdx.x * blockDim.x + threadIdx.x) >> 5;
    const int nwrp  = (gridDim.x * blockDim.x) >> 5;

    // Per-lane weights in registers, constants folded:
    //   edge_w + 1 = (w0[i]+1) + (2*wc[i,:])·P + (2*ws[i,:])·Q
    float wcr[Kk], wsr[Kk];
#pragma unroll
    for (int k = 0; k < Kk; k++) {
        wcr[k] = 2.0f * __ldg(&wc[(lane * Kk + k) * Mm + m]);
        wsr[k] = 2.0f * __ldg(&ws[(lane * Kk + k) * Mm + m]);
    }
    const float w0r = __ldg(&w0[lane * Mm + m]) + 1.0f;

    const float2* nodes2 = reinterpret_cast<const float2*>(nodes);
    const float2* nvec2  = reinterpret_cast<const float2*>(nvec);

    for (int b = 0; b < Bsz; b++) {
        for (int e = warp; e < Ee; e += nwrp) {
            const long eb = ((long)b * Ee + e);
            const int t = __ldg(&de[eb * 2 * Mm + m]);
            const int s = __ldg(&de[eb * 2 * Mm + Mm + m]);
            const long bt = (long)b * Nn + t;
            const long bs = (long)b * Nn + s;

            // geometry (uniform across warp; broadcast loads)
            const float2 pt = nodes2[bt];
            const float2 ps = nodes2[bs];
            const float2 nv = nvec2[bs];
            const float dx = pt.x - ps.x, dy = pt.y - ps.y;
            const float r2 = fmaf(dx, dx, fmaf(dy, dy, 1e-6f));
            const float gr = fmaf(dx, nv.x, dy * nv.y) / r2;
            const float sgeo = gr * __ldg(&nodew[eb * Mm + m]);

            // lanes 0..15: load bases (each gather = one 128B line) and
            // compute P[k] = bc_t*bc_s + bs_t*bs_s, Q[k] = bc_t*bs_s - bs_t*bc_s
            float P = 0.0f, Q = 0.0f;
            if (lane < Kk) {
                const float bct = __ldg(&bases_c[(bt * Kk + lane) * Mm + m]);
                const float bst = __ldg(&bases_s[(bt * Kk + lane) * Mm + m]);
                const float bcs = __ldg(&bases_c[(bs * Kk + lane) * Mm + m]);
                const float bss = __ldg(&bases_s[(bs * Kk + lane) * Mm + m]);
                P = fmaf(bct, bcs, bst * bss);
                Q = fmaf(bct, bss, -bst * bcs);
            }

            // per-channel edge weight via shuffle broadcast
            float ew = w0r;
#pragma unroll
            for (int k = 0; k < Kk; k++) {
                const float p = __shfl_sync(0xffffffffu, P, k);
                const float q = __shfl_sync(0xffffffffu, Q, k);
                ew = fmaf(wcr[k], p, ew);
                ew = fmaf(wsr[k], q, ew);
            }

            const float fs  = g_fT[bs * CINc + lane];
            const float val = ew * fs * sgeo;

            // pack 4 channels per lane -> one 16B vector atomic
            const float v1 = __shfl_down_sync(0xffffffffu, val, 1);
            const float v2 = __shfl_down_sync(0xffffffffu, val, 2);
            const float v3 = __shfl_down_sync(0xffffffffu, val, 3);
            if ((lane & 3) == 0) {
                float* dst = &g_fout[bt * CINc + lane];
                asm volatile(
                    "red.global.add.v4.f32 [%0], {%1, %2, %3, %4};"
                    :: "l"(dst), "f"(val), "f"(v1), "f"(v2), "f"(v3)
                    : "memory");
            }
        }
    }
}

// ---------------------------------------------------------------------------
// Kernel 3: out[b,o,n] = sum_i w[o,i] * f_out[b,n,i] + bias[o]
// grid (N/32=625, B), block 256. 32-node tile in smem.
// ---------------------------------------------------------------------------
__global__ void __launch_bounds__(256) out_kernel(
    const float* __restrict__ wk,
    const float* __restrict__ bias,
    float* __restrict__ out)
{
    __shared__ float fsm[32][33];
    __shared__ float wsm[COUTc][CINc];

    const int b   = blockIdx.y;
    const int n0  = blockIdx.x * 32;
    const int tid = threadIdx.x;

    for (int j = tid; j < COUTc * CINc; j += 256)
        wsm[j / CINc][j % CINc] = wk[j];

#pragma unroll
    for (int j = 0; j < 4; j++) {
        int idx = j * 256 + tid;
        int nl = idx >> 5, i = idx & 31;
        fsm[nl][i] = g_fout[((long)b * Nn + n0 + nl) * CINc + i];
    }
    __syncthreads();

#pragma unroll
    for (int j = 0; j < 4; j++) {
        int idx = j * 256 + tid;
        int o = idx >> 5, nl = idx & 31;   // o uniform within warp
        float acc = bias[o];
#pragma unroll
        for (int i = 0; i < CINc; i++)
            acc = fmaf(wsm[o][i], fsm[nl][i], acc);
        out[((long)b * COUTc + o) * Nn + n0 + nl] = acc;
    }
}

// ---------------------------------------------------------------------------
// Launch. Input order (metadata): f, bases_c, bases_s, bases_0(unused), nodes,
// normal_vectors, directed_edges, node_weights, weights_c, weights_s,
// weights_0, w_kernel, w_bias.
// ---------------------------------------------------------------------------
extern "C" void kernel_launch(void* const* d_in, const int* in_sizes, int n_in,
                              void* d_out, int out_size)
{
    const float* f    = (const float*)d_in[0];
    const float* bc   = (const float*)d_in[1];
    const float* bs   = (const float*)d_in[2];
    const float* nodes= (const float*)d_in[4];
    const float* nvec = (const float*)d_in[5];
    const int*   de   = (const int*)  d_in[6];
    const float* nw   = (const float*)d_in[7];
    const float* wc   = (const float*)d_in[8];
    const float* ws   = (const float*)d_in[9];
    const float* w0   = (const float*)d_in[10];
    const float* wk   = (const float*)d_in[11];
    const float* wb   = (const float*)d_in[12];
    float* out = (float*)d_out;

    prep_kernel<<<dim3(Nn / 32, Bsz), dim3(32, 8)>>>(f);
    edge_kernel<<<dim3(1480, 2), 256>>>(bc, bs, nodes, nvec, de, nw, wc, ws, w0);
    out_kernel<<<dim3(Nn / 32, Bsz), 256>>>(wk, wb, out);
}

// round 2
// speedup vs baseline: 1.6470x; 1.6470x over previous
#include <cuda_runtime.h>

#define Bsz   4
#define Nn    20000
#define Ee    320000
#define CINc  32
#define COUTc 32
#define Kk    16
#define Mm    2

// Scratch: fT (B,N,CIN) and f_out accumulator (B,N,CIN)
__device__ float g_fT[Bsz * Nn * CINc];
__device__ float g_fout[Bsz * Nn * CINc];

__device__ __forceinline__ unsigned f2tf32(float x) {
    unsigned u;
    asm("cvt.rna.tf32.f32 %0, %1;" : "=r"(u) : "f"(x));
    return u;
}

__device__ __forceinline__ void mma_tf32(float c[4], const unsigned a[4], const unsigned b[2]) {
    asm volatile(
        "mma.sync.aligned.m16n8k8.row.col.f32.tf32.tf32.f32 "
        "{%0,%1,%2,%3}, {%4,%5,%6,%7}, {%8,%9}, {%0,%1,%2,%3};"
        : "+f"(c[0]), "+f"(c[1]), "+f"(c[2]), "+f"(c[3])
        : "r"(a[0]), "r"(a[1]), "r"(a[2]), "r"(a[3]), "r"(b[0]), "r"(b[1]));
}

// ---------------------------------------------------------------------------
// Kernel 1: transpose f (B,CIN,N) -> fT (B,N,CIN), zero f_out
// ---------------------------------------------------------------------------
__global__ void prep_kernel(const float* __restrict__ f)
{
    __shared__ float tile[32][33];
    const int b  = blockIdx.y;
    const int n0 = blockIdx.x * 32;
    const int tx = threadIdx.x;
    const int ty = threadIdx.y;

#pragma unroll
    for (int r = 0; r < 4; r++) {
        int ci = ty + 8 * r;
        tile[ci][tx] = f[((long)b * CINc + ci) * Nn + n0 + tx];
    }
    __syncthreads();
#pragma unroll
    for (int r = 0; r < 4; r++) {
        int nl = ty + 8 * r;
        long idx = ((long)b * Nn + n0 + nl) * CINc + tx;
        g_fT[idx]   = tile[tx][nl];
        g_fout[idx] = 0.0f;
    }
}

// ---------------------------------------------------------------------------
// W matrix element: Wmat[r][c], c<16 -> 2*wc[r][c], c>=16 -> 2*ws[r][c-16]
// ---------------------------------------------------------------------------
__device__ __forceinline__ float loadW(const float* __restrict__ wc,
                                       const float* __restrict__ ws,
                                       int r, int c, int m)
{
    return (c < 16) ? 2.0f * __ldg(&wc[r * 32 + c * 2 + m])
                    : 2.0f * __ldg(&ws[r * 32 + (c - 16) * 2 + m]);
}

// ---------------------------------------------------------------------------
// Kernel 2: edge scatter, mma-based. One warp per 32-edge tile.
// Grid: 2500 blocks x 128 threads = 10000 warps; 5000 per measure m.
// Tiles per m: 4 batches * 10000 = 40000 -> 8 tiles per warp.
// ---------------------------------------------------------------------------
__global__ void __launch_bounds__(128) edge_kernel(
    const float* __restrict__ bases_c,
    const float* __restrict__ bases_s,
    const float* __restrict__ nodes,
    const float* __restrict__ nvec,
    const int*   __restrict__ de,
    const float* __restrict__ nodew,
    const float* __restrict__ wc,
    const float* __restrict__ ws,
    const float* __restrict__ w0)
{
    __shared__ float pqs[4][32][33];

    const int lane = threadIdx.x & 31;
    const int wid  = threadIdx.x >> 5;
    float (*pq)[33] = pqs[wid];

    const int gw = blockIdx.x * 4 + wid;          // 0..9999
    const int WPM = 5000;                          // warps per measure
    const int m      = gw / WPM;                   // 0 or 1
    const int w_in_m = gw % WPM;

    const int gid = lane >> 2;    // 0..7
    const int tq  = lane & 3;     // 0..3

    // --- persistent A fragments: W (32x32) in tf32, per (mt, kstep) ---
    unsigned afr[2][4][4];
#pragma unroll
    for (int mt = 0; mt < 2; mt++)
#pragma unroll
        for (int ks = 0; ks < 4; ks++) {
            const int r0 = mt * 16 + gid, r1 = r0 + 8;
            const int c0 = ks * 8 + tq,  c1 = c0 + 4;
            afr[mt][ks][0] = f2tf32(loadW(wc, ws, r0, c0, m));
            afr[mt][ks][1] = f2tf32(loadW(wc, ws, r1, c0, m));
            afr[mt][ks][2] = f2tf32(loadW(wc, ws, r0, c1, m));
            afr[mt][ks][3] = f2tf32(loadW(wc, ws, r1, c1, m));
        }
    const float w0r = __ldg(&w0[lane * 2 + m]) + 1.0f;

    const float2* nodes2 = reinterpret_cast<const float2*>(nodes);
    const float2* nvec2  = reinterpret_cast<const float2*>(nvec);

    const int khalf = lane & 15;   // k index in PQ phase
    const int hi    = lane >> 4;   // 0 -> P, 1 -> Q

    for (int tidx = w_in_m; tidx < 4 * (Ee / 32); tidx += WPM) {
        const int b  = tidx / (Ee / 32);
        const int e0 = (tidx % (Ee / 32)) * 32;

        // ---- geometry phase: lane = edge ----
        const long eb = (long)b * Ee + e0 + lane;
        const int t = __ldg(&de[eb * 4 + m]);
        const int s = __ldg(&de[eb * 4 + 2 + m]);
        const int tn = b * Nn + t;
        const int sn = b * Nn + s;
        const float2 pt = nodes2[tn];
        const float2 ps = nodes2[sn];
        const float2 nv = nvec2[sn];
        const float dx = pt.x - ps.x, dy = pt.y - ps.y;
        const float r2 = fmaf(dx, dx, fmaf(dy, dy, 1e-6f));
        const float gr = fmaf(dx, nv.x, dy * nv.y) / r2;
        const float sgeo = gr * __ldg(&nodew[eb * 2 + m]);

        // ---- PQ phase: full warp per edge, lanes 0-15 P, 16-31 Q ----
#pragma unroll
        for (int e = 0; e < 32; e++) {
            const int tne = __shfl_sync(0xffffffffu, tn, e);
            const int sne = __shfl_sync(0xffffffffu, sn, e);
            const float bct = __ldg(&bases_c[(long)tne * 32 + khalf * 2 + m]);
            const float bst = __ldg(&bases_s[(long)tne * 32 + khalf * 2 + m]);
            const float bcs = __ldg(&bases_c[(long)sne * 32 + khalf * 2 + m]);
            const float bss = __ldg(&bases_s[(long)sne * 32 + khalf * 2 + m]);
            const float v = hi ? fmaf(bct, bss, -bst * bcs)
                               : fmaf(bct, bcs,  bst * bss);
            pq[e][lane] = __uint_as_float(f2tf32(v));
        }
        __syncwarp();

        // ---- MMA phase: EW[32ch][32edges] = W * PQ^T ----
        float acc[2][4][4];
#pragma unroll
        for (int mt = 0; mt < 2; mt++)
#pragma unroll
            for (int nt = 0; nt < 4; nt++)
#pragma unroll
                for (int r = 0; r < 4; r++) acc[mt][nt][r] = 0.0f;

#pragma unroll
        for (int nt = 0; nt < 4; nt++) {
            unsigned bfr[4][2];
#pragma unroll
            for (int ks = 0; ks < 4; ks++) {
                bfr[ks][0] = __float_as_uint(pq[nt * 8 + gid][ks * 8 + tq]);
                bfr[ks][1] = __float_as_uint(pq[nt * 8 + gid][ks * 8 + tq + 4]);
            }
#pragma unroll
            for (int mt = 0; mt < 2; mt++)
#pragma unroll
                for (int ks = 0; ks < 4; ks++)
                    mma_tf32(acc[mt][nt], afr[mt][ks], bfr[ks]);
        }
        __syncwarp();

        // ---- write EW back to smem: ew[edge][ch] (reuse pq buffer) ----
#pragma unroll
        for (int mt = 0; mt < 2; mt++)
#pragma unroll
            for (int nt = 0; nt < 4; nt++) {
                const int ch = mt * 16 + gid;
                const int ed = nt * 8 + 2 * tq;
                pq[ed][ch]         = acc[mt][nt][0];
                pq[ed + 1][ch]     = acc[mt][nt][1];
                pq[ed][ch + 8]     = acc[mt][nt][2];
                pq[ed + 1][ch + 8] = acc[mt][nt][3];
            }
        __syncwarp();

        // ---- epilogue: lane = channel, v4 vector atomics ----
#pragma unroll
        for (int e = 0; e < 32; e++) {
            const int tne  = __shfl_sync(0xffffffffu, tn, e);
            const int sne  = __shfl_sync(0xffffffffu, sn, e);
            const float sg = __shfl_sync(0xffffffffu, sgeo, e);
            const float fs = g_fT[(long)sne * 32 + lane];
            const float ew = pq[e][lane];
            const float val = (w0r + ew) * fs * sg;
            const float v1 = __shfl_down_sync(0xffffffffu, val, 1);
            const float v2 = __shfl_down_sync(0xffffffffu, val, 2);
            const float v3 = __shfl_down_sync(0xffffffffu, val, 3);
            if (tq == 0) {
                float* dst = &g_fout[(long)tne * 32 + lane];
                asm volatile(
                    "red.global.add.v4.f32 [%0], {%1, %2, %3, %4};"
                    :: "l"(dst), "f"(val), "f"(v1), "f"(v2), "f"(v3)
                    : "memory");
            }
        }
        __syncwarp();
    }
}

// ---------------------------------------------------------------------------
// Kernel 3: out[b,o,n] = sum_i w[o,i] * f_out[b,n,i] + bias[o]
// ---------------------------------------------------------------------------
__global__ void __launch_bounds__(256) out_kernel(
    const float* __restrict__ wk,
    const float* __restrict__ bias,
    float* __restrict__ out)
{
    __shared__ float fsm[32][33];
    __shared__ float wsm[COUTc][CINc];

    const int b   = blockIdx.y;
    const int n0  = blockIdx.x * 32;
    const int tid = threadIdx.x;

    for (int j = tid; j < COUTc * CINc; j += 256)
        wsm[j / CINc][j % CINc] = wk[j];

#pragma unroll
    for (int j = 0; j < 4; j++) {
        int idx = j * 256 + tid;
        int nl = idx >> 5, i = idx & 31;
        fsm[nl][i] = g_fout[((long)b * Nn + n0 + nl) * CINc + i];
    }
    __syncthreads();

#pragma unroll
    for (int j = 0; j < 4; j++) {
        int idx = j * 256 + tid;
        int o = idx >> 5, nl = idx & 31;
        float acc = bias[o];
#pragma unroll
        for (int i = 0; i < CINc; i++)
            acc = fmaf(wsm[o][i], fsm[nl][i], acc);
        out[((long)b * COUTc + o) * Nn + n0 + nl] = acc;
    }
}

// ---------------------------------------------------------------------------
extern "C" void kernel_launch(void* const* d_in, const int* in_sizes, int n_in,
                              void* d_out, int out_size)
{
    const float* f    = (const float*)d_in[0];
    const float* bc   = (const float*)d_in[1];
    const float* bs   = (const float*)d_in[2];
    const float* nodes= (const float*)d_in[4];
    const float* nvec = (const float*)d_in[5];
    const int*   de   = (const int*)  d_in[6];
    const float* nw   = (const float*)d_in[7];
    const float* wc   = (const float*)d_in[8];
    const float* ws   = (const float*)d_in[9];
    const float* w0   = (const float*)d_in[10];
    const float* wk   = (const float*)d_in[11];
    const float* wb   = (const float*)d_in[12];
    float* out = (float*)d_out;

    prep_kernel<<<dim3(Nn / 32, Bsz), dim3(32, 8)>>>(f);
    edge_kernel<<<2500, 128>>>(bc, bs, nodes, nvec, de, nw, wc, ws, w0);
    out_kernel<<<dim3(Nn / 32, Bsz), 256>>>(wk, wb, out);
}

// round 3
// speedup vs baseline: 2.8260x; 1.7158x over previous
#include <cuda_runtime.h>

#define Bsz   4
#define Nn    20000
#define Ee    320000
#define CINc  32
#define COUTc 32
#define Kk    16
#define Mm    2

// Scratch: fT (B,N,CIN) and f_out accumulator (B,N,CIN)
__device__ float g_fT[Bsz * Nn * CINc];
__device__ float g_fout[Bsz * Nn * CINc];

__device__ __forceinline__ unsigned f2tf32(float x) {
    unsigned u;
    asm("cvt.rna.tf32.f32 %0, %1;" : "=r"(u) : "f"(x));
    return u;
}

__device__ __forceinline__ void mma_tf32(float c[4], const unsigned a[4], const unsigned b[2]) {
    asm volatile(
        "mma.sync.aligned.m16n8k8.row.col.f32.tf32.tf32.f32 "
        "{%0,%1,%2,%3}, {%4,%5,%6,%7}, {%8,%9}, {%0,%1,%2,%3};"
        : "+f"(c[0]), "+f"(c[1]), "+f"(c[2]), "+f"(c[3])
        : "r"(a[0]), "r"(a[1]), "r"(a[2]), "r"(a[3]), "r"(b[0]), "r"(b[1]));
}

// ---------------------------------------------------------------------------
// Kernel 1: transpose f (B,CIN,N) -> fT (B,N,CIN), zero f_out
// ---------------------------------------------------------------------------
__global__ void prep_kernel(const float* __restrict__ f)
{
    __shared__ float tile[32][33];
    const int b  = blockIdx.y;
    const int n0 = blockIdx.x * 32;
    const int tx = threadIdx.x;
    const int ty = threadIdx.y;

#pragma unroll
    for (int r = 0; r < 4; r++) {
        int ci = ty + 8 * r;
        tile[ci][tx] = f[((long)b * CINc + ci) * Nn + n0 + tx];
    }
    __syncthreads();
#pragma unroll
    for (int r = 0; r < 4; r++) {
        int nl = ty + 8 * r;
        long idx = ((long)b * Nn + n0 + nl) * CINc + tx;
        g_fT[idx]   = tile[tx][nl];
        g_fout[idx] = 0.0f;
    }
}

// ---------------------------------------------------------------------------
// W matrix element: Wmat[r][c], c<16 -> 2*wc[r][c], c>=16 -> 2*ws[r][c-16]
// ---------------------------------------------------------------------------
__device__ __forceinline__ float loadW(const float* __restrict__ wc,
                                       const float* __restrict__ ws,
                                       int r, int c, int m)
{
    return (c < 16) ? 2.0f * __ldg(&wc[r * 32 + c * 2 + m])
                    : 2.0f * __ldg(&ws[r * 32 + (c - 16) * 2 + m]);
}

// ---------------------------------------------------------------------------
// Kernel 2: edge scatter, mma-based. One warp per 32-edge tile.
// Grid: 2500 blocks x 128 threads = 10000 warps; 5000 per measure m.
// ---------------------------------------------------------------------------
__global__ void __launch_bounds__(128) edge_kernel(
    const float* __restrict__ bases_c,
    const float* __restrict__ bases_s,
    const float* __restrict__ nodes,
    const float* __restrict__ nvec,
    const int*   __restrict__ de,
    const float* __restrict__ nodew,
    const float* __restrict__ wc,
    const float* __restrict__ ws,
    const float* __restrict__ w0)
{
    __shared__ float pqs[4][32][36];    // padded to 36: v4-aligned rows, clean banks
    __shared__ int   tnb[4][32];
    __shared__ int   snb[4][32];
    __shared__ float sgb[4][32];

    const int lane = threadIdx.x & 31;
    const int wid  = threadIdx.x >> 5;
    float (*pq)[36] = pqs[wid];

    const int gw = blockIdx.x * 4 + wid;          // 0..9999
    const int WPM = 5000;                          // warps per measure
    const int m      = gw / WPM;                   // 0 or 1
    const int w_in_m = gw % WPM;

    const int gid = lane >> 2;    // 0..7
    const int tq  = lane & 3;     // 0..3

    // --- persistent A fragments: W (32x32) in tf32, per (mt, kstep) ---
    unsigned afr[2][4][4];
#pragma unroll
    for (int mt = 0; mt < 2; mt++)
#pragma unroll
        for (int ks = 0; ks < 4; ks++) {
            const int r0 = mt * 16 + gid, r1 = r0 + 8;
            const int c0 = ks * 8 + tq,  c1 = c0 + 4;
            afr[mt][ks][0] = f2tf32(loadW(wc, ws, r0, c0, m));
            afr[mt][ks][1] = f2tf32(loadW(wc, ws, r1, c0, m));
            afr[mt][ks][2] = f2tf32(loadW(wc, ws, r0, c1, m));
            afr[mt][ks][3] = f2tf32(loadW(wc, ws, r1, c1, m));
        }

    // epilogue weights: lane handles channels 4g..4g+3, g = lane & 7
    const int g4 = (lane & 7) * 4;
    float w00 = __ldg(&w0[(g4 + 0) * 2 + m]) + 1.0f;
    float w01 = __ldg(&w0[(g4 + 1) * 2 + m]) + 1.0f;
    float w02 = __ldg(&w0[(g4 + 2) * 2 + m]) + 1.0f;
    float w03 = __ldg(&w0[(g4 + 3) * 2 + m]) + 1.0f;

    const float2* nodes2 = reinterpret_cast<const float2*>(nodes);
    const float2* nvec2  = reinterpret_cast<const float2*>(nvec);

    const int khalf = lane & 15;   // k index in PQ phase
    const int hi    = lane >> 4;   // 0 -> P, 1 -> Q

    for (int tidx = w_in_m; tidx < 4 * (Ee / 32); tidx += WPM) {
        const int b  = tidx / (Ee / 32);
        const int e0 = (tidx % (Ee / 32)) * 32;

        // ---- geometry phase: lane = edge ----
        const long eb = (long)b * Ee + e0 + lane;
        const int t = __ldg(&de[eb * 4 + m]);
        const int s = __ldg(&de[eb * 4 + 2 + m]);
        const int tn = b * Nn + t;
        const int sn = b * Nn + s;
        const float2 pt = nodes2[tn];
        const float2 ps = nodes2[sn];
        const float2 nv = nvec2[sn];
        const float dx = pt.x - ps.x, dy = pt.y - ps.y;
        const float r2 = fmaf(dx, dx, fmaf(dy, dy, 1e-6f));
        const float gr = fmaf(dx, nv.x, dy * nv.y) / r2;
        tnb[wid][lane] = tn;
        snb[wid][lane] = sn;
        sgb[wid][lane] = gr * __ldg(&nodew[eb * 2 + m]);

        // ---- PQ phase: full warp per edge, lanes 0-15 P, 16-31 Q ----
#pragma unroll
        for (int e = 0; e < 32; e++) {
            const int tne = __shfl_sync(0xffffffffu, tn, e);
            const int sne = __shfl_sync(0xffffffffu, sn, e);
            const float bct = __ldg(&bases_c[(long)tne * 32 + khalf * 2 + m]);
            const float bst = __ldg(&bases_s[(long)tne * 32 + khalf * 2 + m]);
            const float bcs = __ldg(&bases_c[(long)sne * 32 + khalf * 2 + m]);
            const float bss = __ldg(&bases_s[(long)sne * 32 + khalf * 2 + m]);
            const float v = hi ? fmaf(bct, bss, -bst * bcs)
                               : fmaf(bct, bcs,  bst * bss);
            pq[e][lane] = __uint_as_float(f2tf32(v));
        }
        __syncwarp();

        // ---- MMA phase: EW[32ch][32edges] = W * PQ^T, nt-sequential ----
#pragma unroll
        for (int nt = 0; nt < 4; nt++) {
            unsigned bfr[4][2];
#pragma unroll
            for (int ks = 0; ks < 4; ks++) {
                bfr[ks][0] = __float_as_uint(pq[nt * 8 + gid][ks * 8 + tq]);
                bfr[ks][1] = __float_as_uint(pq[nt * 8 + gid][ks * 8 + tq + 4]);
            }
            __syncwarp();
#pragma unroll
            for (int mt = 0; mt < 2; mt++) {
                float acc[4] = {0.0f, 0.0f, 0.0f, 0.0f};
#pragma unroll
                for (int ks = 0; ks < 4; ks++)
                    mma_tf32(acc, afr[mt][ks], bfr[ks]);
                // write EW back: ew[edge][ch] (reuse pq rows of this nt)
                const int ch = mt * 16 + gid;
                const int ed = nt * 8 + 2 * tq;
                pq[ed][ch]         = acc[0];
                pq[ed + 1][ch]     = acc[1];
                pq[ed][ch + 8]     = acc[2];
                pq[ed + 1][ch + 8] = acc[3];
            }
        }
        __syncwarp();

        // ---- epilogue: lane = (edge-subgroup, 4-channel group), v4 atomics ----
#pragma unroll
        for (int it = 0; it < 8; it++) {
            const int e   = it * 4 + (lane >> 3);
            const int tne = tnb[wid][e];
            const int sne = snb[wid][e];
            const float sg = sgb[wid][e];
            const float4 fs = *reinterpret_cast<const float4*>(&g_fT[(long)sne * 32 + g4]);
            const float4 ew = *reinterpret_cast<const float4*>(&pq[e][g4]);
            const float v0 = (w00 + ew.x) * fs.x * sg;
            const float v1 = (w01 + ew.y) * fs.y * sg;
            const float v2 = (w02 + ew.z) * fs.z * sg;
            const float v3 = (w03 + ew.w) * fs.w * sg;
            float* dst = &g_fout[(long)tne * 32 + g4];
            asm volatile(
                "red.global.add.v4.f32 [%0], {%1, %2, %3, %4};"
                :: "l"(dst), "f"(v0), "f"(v1), "f"(v2), "f"(v3)
                : "memory");
        }
        __syncwarp();
    }
}

// ---------------------------------------------------------------------------
// Kernel 3: out[b,o,n] = sum_i w[o,i] * f_out[b,n,i] + bias[o]
// ---------------------------------------------------------------------------
__global__ void __launch_bounds__(256) out_kernel(
    const float* __restrict__ wk,
    const float* __restrict__ bias,
    float* __restrict__ out)
{
    __shared__ float fsm[32][33];
    __shared__ float wsm[COUTc][CINc];

    const int b   = blockIdx.y;
    const int n0  = blockIdx.x * 32;
    const int tid = threadIdx.x;

    for (int j = tid; j < COUTc * CINc; j += 256)
        wsm[j / CINc][j % CINc] = wk[j];

#pragma unroll
    for (int j = 0; j < 4; j++) {
        int idx = j * 256 + tid;
        int nl = idx >> 5, i = idx & 31;
        fsm[nl][i] = g_fout[((long)b * Nn + n0 + nl) * CINc + i];
    }
    __syncthreads();

#pragma unroll
    for (int j = 0; j < 4; j++) {
        int idx = j * 256 + tid;
        int o = idx >> 5, nl = idx & 31;
        float acc = bias[o];
#pragma unroll
        for (int i = 0; i < CINc; i++)
            acc = fmaf(wsm[o][i], fsm[nl][i], acc);
        out[((long)b * COUTc + o) * Nn + n0 + nl] = acc;
    }
}

// ---------------------------------------------------------------------------
extern "C" void kernel_launch(void* const* d_in, const int* in_sizes, int n_in,
                              void* d_out, int out_size)
{
    const float* f    = (const float*)d_in[0];
    const float* bc   = (const float*)d_in[1];
    const float* bs   = (const float*)d_in[2];
    const float* nodes= (const float*)d_in[4];
    const float* nvec = (const float*)d_in[5];
    const int*   de   = (const int*)  d_in[6];
    const float* nw   = (const float*)d_in[7];
    const float* wc   = (const float*)d_in[8];
    const float* ws   = (const float*)d_in[9];
    const float* w0   = (const float*)d_in[10];
    const float* wk   = (const float*)d_in[11];
    const float* wb   = (const float*)d_in[12];
    float* out = (float*)d_out;

    prep_kernel<<<dim3(Nn / 32, Bsz), dim3(32, 8)>>>(f);
    edge_kernel<<<2500, 128>>>(bc, bs, nodes, nvec, de, nw, wc, ws, w0);
    out_kernel<<<dim3(Nn / 32, Bsz), 256>>>(wk, wb, out);
}

// round 4
// speedup vs baseline: 3.3275x; 1.1775x over previous
#include <cuda_runtime.h>

#define Bsz   4
#define Nn    20000
#define Ee    320000
#define CINc  32
#define COUTc 32
#define Kk    16
#define Mm    2

// Scratch: fT (B,N,CIN) and f_out accumulator (B,N,CIN)
__device__ float g_fT[Bsz * Nn * CINc];
__device__ float g_fout[Bsz * Nn * CINc];

__device__ __forceinline__ unsigned f2tf32(float x) {
    unsigned u;
    asm("cvt.rna.tf32.f32 %0, %1;" : "=r"(u) : "f"(x));
    return u;
}

__device__ __forceinline__ void mma_tf32(float c[4], const unsigned a[4], const unsigned b[2]) {
    asm volatile(
        "mma.sync.aligned.m16n8k8.row.col.f32.tf32.tf32.f32 "
        "{%0,%1,%2,%3}, {%4,%5,%6,%7}, {%8,%9}, {%0,%1,%2,%3};"
        : "+f"(c[0]), "+f"(c[1]), "+f"(c[2]), "+f"(c[3])
        : "r"(a[0]), "r"(a[1]), "r"(a[2]), "r"(a[3]), "r"(b[0]), "r"(b[1]));
}

// ---------------------------------------------------------------------------
// Kernel 1: transpose f (B,CIN,N) -> fT (B,N,CIN), zero f_out
// ---------------------------------------------------------------------------
__global__ void prep_kernel(const float* __restrict__ f)
{
    __shared__ float tile[32][33];
    const int b  = blockIdx.y;
    const int n0 = blockIdx.x * 32;
    const int tx = threadIdx.x;
    const int ty = threadIdx.y;

#pragma unroll
    for (int r = 0; r < 4; r++) {
        int ci = ty + 8 * r;
        tile[ci][tx] = f[((long)b * CINc + ci) * Nn + n0 + tx];
    }
    __syncthreads();
#pragma unroll
    for (int r = 0; r < 4; r++) {
        int nl = ty + 8 * r;
        long idx = ((long)b * Nn + n0 + nl) * CINc + tx;
        g_fT[idx]   = tile[tx][nl];
        g_fout[idx] = 0.0f;
    }
}

// ---------------------------------------------------------------------------
// W matrix element: Wmat[r][c], c<16 -> 2*wc[r][c], c>=16 -> 2*ws[r][c-16]
// ---------------------------------------------------------------------------
__device__ __forceinline__ float loadW(const float* __restrict__ wc,
                                       const float* __restrict__ ws,
                                       int r, int c, int m)
{
    return (c < 16) ? 2.0f * __ldg(&wc[r * 32 + c * 2 + m])
                    : 2.0f * __ldg(&ws[r * 32 + (c - 16) * 2 + m]);
}

// ---------------------------------------------------------------------------
// Kernel 2: edge scatter, mma-based. One warp per 32-edge tile.
// Grid: 2500 blocks x 128 threads = 10000 warps; 5000 per measure m.
// ---------------------------------------------------------------------------
__global__ void __launch_bounds__(128) edge_kernel(
    const float* __restrict__ bases_c,
    const float* __restrict__ bases_s,
    const float* __restrict__ nodes,
    const float* __restrict__ nvec,
    const int*   __restrict__ de,
    const float* __restrict__ nodew,
    const float* __restrict__ wc,
    const float* __restrict__ ws,
    const float* __restrict__ w0)
{
    __shared__ float pqs[4][32][36];    // padded: v4-aligned rows, clean banks
    __shared__ int2  nsb[4][32];        // {tn, sn} per edge
    __shared__ float sgb[4][32];

    const int lane = threadIdx.x & 31;
    const int wid  = threadIdx.x >> 5;
    float (*pq)[36] = pqs[wid];

    const int gw = blockIdx.x * 4 + wid;          // 0..9999
    const int WPM = 5000;                          // warps per measure
    const int m      = gw / WPM;                   // 0 or 1
    const int w_in_m = gw % WPM;

    const int gid = lane >> 2;    // 0..7
    const int tq  = lane & 3;     // 0..3

    // --- persistent A fragments: W (32x32) in tf32, per (mt, kstep) ---
    unsigned afr[2][4][4];
#pragma unroll
    for (int mt = 0; mt < 2; mt++)
#pragma unroll
        for (int ks = 0; ks < 4; ks++) {
            const int r0 = mt * 16 + gid, r1 = r0 + 8;
            const int c0 = ks * 8 + tq,  c1 = c0 + 4;
            afr[mt][ks][0] = f2tf32(loadW(wc, ws, r0, c0, m));
            afr[mt][ks][1] = f2tf32(loadW(wc, ws, r1, c0, m));
            afr[mt][ks][2] = f2tf32(loadW(wc, ws, r0, c1, m));
            afr[mt][ks][3] = f2tf32(loadW(wc, ws, r1, c1, m));
        }

    // epilogue weights: lane handles channels 4g..4g+3, g = lane & 7
    const int g4 = (lane & 7) * 4;
    const float w00 = __ldg(&w0[(g4 + 0) * 2 + m]) + 1.0f;
    const float w01 = __ldg(&w0[(g4 + 1) * 2 + m]) + 1.0f;
    const float w02 = __ldg(&w0[(g4 + 2) * 2 + m]) + 1.0f;
    const float w03 = __ldg(&w0[(g4 + 3) * 2 + m]) + 1.0f;

    const float2* nodes2 = reinterpret_cast<const float2*>(nodes);
    const float2* nvec2  = reinterpret_cast<const float2*>(nvec);

    // PQ-phase lane decomposition
    const int ph = (lane >> 4) & 1;   // which edge of the pair
    const int pp = (lane >> 3) & 1;   // 0 = target role, 1 = source role
    const int pj = lane & 7;          // float4 index within 128B row

    for (int tidx = w_in_m; tidx < 4 * (Ee / 32); tidx += WPM) {
        const int b  = tidx / (Ee / 32);
        const int e0 = (tidx % (Ee / 32)) * 32;

        // ---- geometry phase: lane = edge ----
        const long eb = (long)b * Ee + e0 + lane;
        const int t = __ldg(&de[eb * 4 + m]);
        const int s = __ldg(&de[eb * 4 + 2 + m]);
        const int tn = b * Nn + t;
        const int sn = b * Nn + s;
        const float2 pt = nodes2[tn];
        const float2 ps = nodes2[sn];
        const float2 nv = nvec2[sn];
        const float dx = pt.x - ps.x, dy = pt.y - ps.y;
        const float r2 = fmaf(dx, dx, fmaf(dy, dy, 1e-6f));
        const float gr = fmaf(dx, nv.x, dy * nv.y) / r2;
        nsb[wid][lane] = make_int2(tn, sn);
        sgb[wid][lane] = gr * __ldg(&nodew[eb * 2 + m]);
        __syncwarp();

        // ---- PQ phase: 16 pair-iterations, 2 edges each.
        // lane (ph,pp,pj): row = bases of (pp? source : target) node of edge
        // 2*pr+ph, float4 pj. All LDG.128 independent (addresses from smem).
#pragma unroll
        for (int pr = 0; pr < 16; pr++) {
            const int e    = pr * 2 + ph;
            const int node = pp ? nsb[wid][e].y : nsb[wid][e].x;
            const float4 A = *reinterpret_cast<const float4*>(&bases_c[(long)node * 32 + pj * 4]);
            const float4 B = *reinterpret_cast<const float4*>(&bases_s[(long)node * 32 + pj * 4]);
            // select this warp's measure: m=0 -> (x,z), m=1 -> (y,w)
            const float a0 = m ? A.y : A.x, a1 = m ? A.w : A.z;
            const float b0 = m ? B.y : B.x, b1 = m ? B.w : B.z;
            // exchange target<->source halves
            const float a0o = __shfl_xor_sync(0xffffffffu, a0, 8);
            const float a1o = __shfl_xor_sync(0xffffffffu, a1, 8);
            const float b0o = __shfl_xor_sync(0xffffffffu, b0, 8);
            const float b1o = __shfl_xor_sync(0xffffffffu, b1, 8);
            // p=0 lanes: P = bct*bcs + bst*bss
            // p=1 lanes: Q = bct*bss - bst*bcs = b*a' - a*b' (own=source)
            const float r0 = pp ? fmaf(b0, a0o, -(a0 * b0o))
                                : fmaf(a0, a0o,  (b0 * b0o));
            const float r1 = pp ? fmaf(b1, a1o, -(a1 * b1o))
                                : fmaf(a1, a1o,  (b1 * b1o));
            // store tf32-rounded pair: P at [k..], Q at [16+k..], k = 2*pj
            float2* dst = reinterpret_cast<float2*>(&pq[e][pp * 16 + 2 * pj]);
            *dst = make_float2(__uint_as_float(f2tf32(r0)),
                               __uint_as_float(f2tf32(r1)));
        }
        __syncwarp();

        // ---- MMA phase: EW[32ch][32edges] = W * PQ^T, nt-sequential ----
#pragma unroll
        for (int nt = 0; nt < 4; nt++) {
            unsigned bfr[4][2];
#pragma unroll
            for (int ks = 0; ks < 4; ks++) {
                bfr[ks][0] = __float_as_uint(pq[nt * 8 + gid][ks * 8 + tq]);
                bfr[ks][1] = __float_as_uint(pq[nt * 8 + gid][ks * 8 + tq + 4]);
            }
            __syncwarp();
#pragma unroll
            for (int mt = 0; mt < 2; mt++) {
                float acc[4] = {0.0f, 0.0f, 0.0f, 0.0f};
#pragma unroll
                for (int ks = 0; ks < 4; ks++)
                    mma_tf32(acc, afr[mt][ks], bfr[ks]);
                const int ch = mt * 16 + gid;
                const int ed = nt * 8 + 2 * tq;
                pq[ed][ch]         = acc[0];
                pq[ed + 1][ch]     = acc[1];
                pq[ed][ch + 8]     = acc[2];
                pq[ed + 1][ch + 8] = acc[3];
            }
        }
        __syncwarp();

        // ---- epilogue: lane = (edge-subgroup, 4-channel group), v4 atomics ----
#pragma unroll
        for (int it = 0; it < 8; it++) {
            const int e    = it * 4 + (lane >> 3);
            const int2 ns  = nsb[wid][e];
            const float sg = sgb[wid][e];
            const float4 fs = *reinterpret_cast<const float4*>(&g_fT[(long)ns.y * 32 + g4]);
            const float4 ew = *reinterpret_cast<const float4*>(&pq[e][g4]);
            const float v0 = (w00 + ew.x) * fs.x * sg;
            const float v1 = (w01 + ew.y) * fs.y * sg;
            const float v2 = (w02 + ew.z) * fs.z * sg;
            const float v3 = (w03 + ew.w) * fs.w * sg;
            float* dst = &g_fout[(long)ns.x * 32 + g4];
            asm volatile(
                "red.global.add.v4.f32 [%0], {%1, %2, %3, %4};"
                :: "l"(dst), "f"(v0), "f"(v1), "f"(v2), "f"(v3)
                : "memory");
        }
        __syncwarp();
    }
}

// ---------------------------------------------------------------------------
// Kernel 3: out[b,o,n] = sum_i w[o,i] * f_out[b,n,i] + bias[o]
// ---------------------------------------------------------------------------
__global__ void __launch_bounds__(256) out_kernel(
    const float* __restrict__ wk,
    const float* __restrict__ bias,
    float* __restrict__ out)
{
    __shared__ float fsm[32][33];
    __shared__ float wsm[COUTc][CINc];

    const int b   = blockIdx.y;
    const int n0  = blockIdx.x * 32;
    const int tid = threadIdx.x;

    for (int j = tid; j < COUTc * CINc; j += 256)
        wsm[j / CINc][j % CINc] = wk[j];

#pragma unroll
    for (int j = 0; j < 4; j++) {
        int idx = j * 256 + tid;
        int nl = idx >> 5, i = idx & 31;
        fsm[nl][i] = g_fout[((long)b * Nn + n0 + nl) * CINc + i];
    }
    __syncthreads();

#pragma unroll
    for (int j = 0; j < 4; j++) {
        int idx = j * 256 + tid;
        int o = idx >> 5, nl = idx & 31;
        float acc = bias[o];
#pragma unroll
        for (int i = 0; i < CINc; i++)
            acc = fmaf(wsm[o][i], fsm[nl][i], acc);
        out[((long)b * COUTc + o) * Nn + n0 + nl] = acc;
    }
}

// ---------------------------------------------------------------------------
extern "C" void kernel_launch(void* const* d_in, const int* in_sizes, int n_in,
                              void* d_out, int out_size)
{
    const float* f    = (const float*)d_in[0];
    const float* bc   = (const float*)d_in[1];
    const float* bs   = (const float*)d_in[2];
    const float* nodes= (const float*)d_in[4];
    const float* nvec = (const float*)d_in[5];
    const int*   de   = (const int*)  d_in[6];
    const float* nw   = (const float*)d_in[7];
    const float* wc   = (const float*)d_in[8];
    const float* ws   = (const float*)d_in[9];
    const float* w0   = (const float*)d_in[10];
    const float* wk   = (const float*)d_in[11];
    const float* wb   = (const float*)d_in[12];
    float* out = (float*)d_out;

    prep_kernel<<<dim3(Nn / 32, Bsz), dim3(32, 8)>>>(f);
    edge_kernel<<<2500, 128>>>(bc, bs, nodes, nvec, de, nw, wc, ws, w0);
    out_kernel<<<dim3(Nn / 32, Bsz), 256>>>(wk, wb, out);
}

// round 5
// speedup vs baseline: 3.4850x; 1.0473x over previous
#include <cuda_runtime.h>

#define Bsz   4
#define Nn    20000
#define Ee    320000
#define CINc  32
#define COUTc 32
#define Kk    16
#define Mm    2

// Scratch
__device__ float g_fT[Bsz * Nn * CINc];                 // (B,N,CIN)
__device__ float g_fout[Bsz * Nn * CINc];               // (B,N,CIN)
__device__ float g_comb[Mm * Bsz * Nn * 2 * Kk];        // [m][b*N+n][k2]{bc,bs} : 128B/row

__device__ __forceinline__ unsigned f2tf32(float x) {
    unsigned u;
    asm("cvt.rna.tf32.f32 %0, %1;" : "=r"(u) : "f"(x));
    return u;
}

__device__ __forceinline__ void mma_tf32(float c[4], const unsigned a[4], const unsigned b[2]) {
    asm volatile(
        "mma.sync.aligned.m16n8k8.row.col.f32.tf32.tf32.f32 "
        "{%0,%1,%2,%3}, {%4,%5,%6,%7}, {%8,%9}, {%0,%1,%2,%3};"
        : "+f"(c[0]), "+f"(c[1]), "+f"(c[2]), "+f"(c[3])
        : "r"(a[0]), "r"(a[1]), "r"(a[2]), "r"(a[3]), "r"(b[0]), "r"(b[1]));
}

// ---------------------------------------------------------------------------
// Kernel 1: transpose f (B,CIN,N) -> fT, zero f_out, and repack bases:
//   comb[m][node][4*pj..] = (bc[2pj],bs[2pj],bc[2pj+1],bs[2pj+1]) for measure m
// ---------------------------------------------------------------------------
__global__ void prep_kernel(const float* __restrict__ f,
                            const float* __restrict__ bc,
                            const float* __restrict__ bs)
{
    __shared__ float tile[32][33];
    const int b   = blockIdx.y;
    const int n0  = blockIdx.x * 32;
    const int tx  = threadIdx.x;
    const int ty  = threadIdx.y;
    const int tid = ty * 32 + tx;

#pragma unroll
    for (int r = 0; r < 4; r++) {
        int ci = ty + 8 * r;
        tile[ci][tx] = f[((long)b * CINc + ci) * Nn + n0 + tx];
    }

    // bases repack: 256 threads cover 32 nodes x 8 quads
    {
        const int nl = tid >> 3;          // node within tile
        const int pj = tid & 7;           // float4 index in 128B row
        const long node = (long)b * Nn + n0 + nl;
        const float4 A = *reinterpret_cast<const float4*>(&bc[node * 32 + pj * 4]);
        const float4 B = *reinterpret_cast<const float4*>(&bs[node * 32 + pj * 4]);
        float4* c0 = reinterpret_cast<float4*>(&g_comb[(0L * Bsz * Nn + node) * 32 + pj * 4]);
        float4* c1 = reinterpret_cast<float4*>(&g_comb[(1L * Bsz * Nn + node) * 32 + pj * 4]);
        *c0 = make_float4(A.x, B.x, A.z, B.z);   // m = 0
        *c1 = make_float4(A.y, B.y, A.w, B.w);   // m = 1
    }

    __syncthreads();
#pragma unroll
    for (int r = 0; r < 4; r++) {
        int nl = ty + 8 * r;
        long idx = ((long)b * Nn + n0 + nl) * CINc + tx;
        g_fT[idx]   = tile[tx][nl];
        g_fout[idx] = 0.0f;
    }
}

// ---------------------------------------------------------------------------
// W matrix element: Wmat[r][c], c<16 -> 2*wc[r][c], c>=16 -> 2*ws[r][c-16]
// ---------------------------------------------------------------------------
__device__ __forceinline__ float loadW(const float* __restrict__ wc,
                                       const float* __restrict__ ws,
                                       int r, int c, int m)
{
    return (c < 16) ? 2.0f * __ldg(&wc[r * 32 + c * 2 + m])
                    : 2.0f * __ldg(&ws[r * 32 + (c - 16) * 2 + m]);
}

// ---------------------------------------------------------------------------
// Kernel 2: edge scatter, mma-based. One warp per 32-edge tile.
// ---------------------------------------------------------------------------
__global__ void __launch_bounds__(128) edge_kernel(
    const float* __restrict__ nodes,
    const float* __restrict__ nvec,
    const int*   __restrict__ de,
    const float* __restrict__ nodew,
    const float* __restrict__ wc,
    const float* __restrict__ ws,
    const float* __restrict__ w0)
{
    __shared__ float pqs[4][32][36];
    __shared__ int2  nsb[4][32];
    __shared__ float sgb[4][32];

    const int lane = threadIdx.x & 31;
    const int wid  = threadIdx.x >> 5;
    float (*pq)[36] = pqs[wid];

    const int gw = blockIdx.x * 4 + wid;
    const int WPM = 5000;
    const int m      = gw / WPM;
    const int w_in_m = gw % WPM;

    const int gid = lane >> 2;
    const int tq  = lane & 3;

    // persistent A fragments: W (32x32) tf32
    unsigned afr[2][4][4];
#pragma unroll
    for (int mt = 0; mt < 2; mt++)
#pragma unroll
        for (int ks = 0; ks < 4; ks++) {
            const int r0 = mt * 16 + gid, r1 = r0 + 8;
            const int c0 = ks * 8 + tq,  c1 = c0 + 4;
            afr[mt][ks][0] = f2tf32(loadW(wc, ws, r0, c0, m));
            afr[mt][ks][1] = f2tf32(loadW(wc, ws, r1, c0, m));
            afr[mt][ks][2] = f2tf32(loadW(wc, ws, r0, c1, m));
            afr[mt][ks][3] = f2tf32(loadW(wc, ws, r1, c1, m));
        }

    const int g4 = (lane & 7) * 4;
    const float w00 = __ldg(&w0[(g4 + 0) * 2 + m]) + 1.0f;
    const float w01 = __ldg(&w0[(g4 + 1) * 2 + m]) + 1.0f;
    const float w02 = __ldg(&w0[(g4 + 2) * 2 + m]) + 1.0f;
    const float w03 = __ldg(&w0[(g4 + 3) * 2 + m]) + 1.0f;

    const float2* nodes2 = reinterpret_cast<const float2*>(nodes);
    const float2* nvec2  = reinterpret_cast<const float2*>(nvec);
    const int4*   de4    = reinterpret_cast<const int4*>(de);
    const float*  comb   = g_comb + (long)m * Bsz * Nn * 32;

    const int ph = (lane >> 4) & 1;
    const int pp = (lane >> 3) & 1;
    const int pj = lane & 7;

    for (int tidx = w_in_m; tidx < 4 * (Ee / 32); tidx += WPM) {
        const int b  = tidx / (Ee / 32);
        const int e0 = (tidx % (Ee / 32)) * 32;

        // ---- geometry: lane = edge; one int4 per edge row ----
        const long eb = (long)b * Ee + e0 + lane;
        const int4 dv = __ldg(&de4[eb]);
        const int t = m ? dv.y : dv.x;
        const int s = m ? dv.w : dv.z;
        const int tn = b * Nn + t;
        const int sn = b * Nn + s;
        const float2 pt = nodes2[tn];
        const float2 ps = nodes2[sn];
        const float2 nv = nvec2[sn];
        const float dx = pt.x - ps.x, dy = pt.y - ps.y;
        const float r2 = fmaf(dx, dx, fmaf(dy, dy, 1e-6f));
        const float gr = fmaf(dx, nv.x, dy * nv.y) / r2;
        nsb[wid][lane] = make_int2(tn, sn);
        sgb[wid][lane] = gr * __ldg(&nodew[eb * 2 + m]);
        __syncwarp();

        // ---- PQ phase: one LDG.128 per lane per pair-iteration ----
#pragma unroll
        for (int pr = 0; pr < 16; pr++) {
            const int e    = pr * 2 + ph;
            const int node = pp ? nsb[wid][e].y : nsb[wid][e].x;
            const float4 A = *reinterpret_cast<const float4*>(&comb[(long)node * 32 + pj * 4]);
            const float a0 = A.x, b0 = A.y, a1 = A.z, b1 = A.w;
            const float a0o = __shfl_xor_sync(0xffffffffu, a0, 8);
            const float a1o = __shfl_xor_sync(0xffffffffu, a1, 8);
            const float b0o = __shfl_xor_sync(0xffffffffu, b0, 8);
            const float b1o = __shfl_xor_sync(0xffffffffu, b1, 8);
            const float r0 = pp ? fmaf(b0, a0o, -(a0 * b0o))
                                : fmaf(a0, a0o,  (b0 * b0o));
            const float r1 = pp ? fmaf(b1, a1o, -(a1 * b1o))
                                : fmaf(a1, a1o,  (b1 * b1o));
            float2* dst = reinterpret_cast<float2*>(&pq[e][pp * 16 + 2 * pj]);
            *dst = make_float2(__uint_as_float(f2tf32(r0)),
                               __uint_as_float(f2tf32(r1)));
        }
        __syncwarp();

        // ---- MMA phase: EW[32ch][32edges] = W * PQ^T ----
#pragma unroll
        for (int nt = 0; nt < 4; nt++) {
            unsigned bfr[4][2];
#pragma unroll
            for (int ks = 0; ks < 4; ks++) {
                bfr[ks][0] = __float_as_uint(pq[nt * 8 + gid][ks * 8 + tq]);
                bfr[ks][1] = __float_as_uint(pq[nt * 8 + gid][ks * 8 + tq + 4]);
            }
            __syncwarp();
#pragma unroll
            for (int mt = 0; mt < 2; mt++) {
                float acc[4] = {0.0f, 0.0f, 0.0f, 0.0f};
#pragma unroll
                for (int ks = 0; ks < 4; ks++)
                    mma_tf32(acc, afr[mt][ks], bfr[ks]);
                const int ch = mt * 16 + gid;
                const int ed = nt * 8 + 2 * tq;
                pq[ed][ch]         = acc[0];
                pq[ed + 1][ch]     = acc[1];
                pq[ed][ch + 8]     = acc[2];
                pq[ed + 1][ch + 8] = acc[3];
            }
        }
        __syncwarp();

        // ---- epilogue: lane = (edge-subgroup, 4-channel group), v4 atomics ----
#pragma unroll
        for (int it = 0; it < 8; it++) {
            const int e    = it * 4 + (lane >> 3);
            const int2 ns  = nsb[wid][e];
            const float sg = sgb[wid][e];
            const float4 fs = *reinterpret_cast<const float4*>(&g_fT[(long)ns.y * 32 + g4]);
            const float4 ew = *reinterpret_cast<const float4*>(&pq[e][g4]);
            const float v0 = (w00 + ew.x) * fs.x * sg;
            const float v1 = (w01 + ew.y) * fs.y * sg;
            const float v2 = (w02 + ew.z) * fs.z * sg;
            const float v3 = (w03 + ew.w) * fs.w * sg;
            float* dst = &g_fout[(long)ns.x * 32 + g4];
            asm volatile(
                "red.global.add.v4.f32 [%0], {%1, %2, %3, %4};"
                :: "l"(dst), "f"(v0), "f"(v1), "f"(v2), "f"(v3)
                : "memory");
        }
        __syncwarp();
    }
}

// ---------------------------------------------------------------------------
// Kernel 3: out[b,o,n] = sum_i w[o,i] * f_out[b,n,i] + bias[o]
// ---------------------------------------------------------------------------
__global__ void __launch_bounds__(256) out_kernel(
    const float* __restrict__ wk,
    const float* __restrict__ bias,
    float* __restrict__ out)
{
    __shared__ float fsm[32][33];
    __shared__ float wsm[COUTc][CINc];

    const int b   = blockIdx.y;
    const int n0  = blockIdx.x * 32;
    const int tid = threadIdx.x;

    for (int j = tid; j < COUTc * CINc; j += 256)
        wsm[j / CINc][j % CINc] = wk[j];

#pragma unroll
    for (int j = 0; j < 4; j++) {
        int idx = j * 256 + tid;
        int nl = idx >> 5, i = idx & 31;
        fsm[nl][i] = g_fout[((long)b * Nn + n0 + nl) * CINc + i];
    }
    __syncthreads();

#pragma unroll
    for (int j = 0; j < 4; j++) {
        int idx = j * 256 + tid;
        int o = idx >> 5, nl = idx & 31;
        float acc = bias[o];
#pragma unroll
        for (int i = 0; i < CINc; i++)
            acc = fmaf(wsm[o][i], fsm[nl][i], acc);
        out[((long)b * COUTc + o) * Nn + n0 + nl] = acc;
    }
}

// ---------------------------------------------------------------------------
extern "C" void kernel_launch(void* const* d_in, const int* in_sizes, int n_in,
                              void* d_out, int out_size)
{
    const float* f    = (const float*)d_in[0];
    const float* bc   = (const float*)d_in[1];
    const float* bs   = (const float*)d_in[2];
    const float* nodes= (const float*)d_in[4];
    const float* nvec = (const float*)d_in[5];
    const int*   de   = (const int*)  d_in[6];
    const float* nw   = (const float*)d_in[7];
    const float* wc   = (const float*)d_in[8];
    const float* ws   = (const float*)d_in[9];
    const float* w0   = (const float*)d_in[10];
    const float* wk   = (const float*)d_in[11];
    const float* wb   = (const float*)d_in[12];
    float* out = (float*)d_out;

    prep_kernel<<<dim3(Nn / 32, Bsz), dim3(32, 8)>>>(f, bc, bs);
    edge_kernel<<<2500, 128>>>(nodes, nvec, de, nw, wc, ws, w0);
    out_kernel<<<dim3(Nn / 32, Bsz), 256>>>(wk, wb, out);
}